// round 6
// baseline (speedup 1.0000x reference)
#include <cuda_runtime.h>
#include <cstdint>

#define SGX 32
#define SGY 24
#define SGT 5
#define NBINS (2 * SGT * SGY * SGX)   // 7680

#define BLOCKS   296                  // 148 SMs x 2 CTAs -> single wave, safe grid sync
#define THREADS  512

#define N_MAX    16777216
#define TQ_MAX   2097151.0f           // 2^21 - 1
#define TQ_SCALE (TQ_MAX / 50.0f)     // t in [0,50] -> [0, 2^21-1]

__device__ uint32_t g_rec[N_MAX];     // 64 MB packed records
__device__ unsigned int g_counts[NBINS];
__device__ unsigned int g_bqmin[BLOCKS];
__device__ unsigned int g_bqmax[BLOCKS];
__device__ unsigned int g_arrive;     // phase-A arrival counter (reset by finalizer)
__device__ unsigned int g_done2;      // phase-B completion counter (reset by finalizer)

// rec = (s << 21) | tq, s = p<<10 | yv<<5 | xv
__device__ __forceinline__ uint32_t pack_event(float4 e, unsigned int& tq) {
    int xv = (int)(e.x * 0.05f);             // 32/640
    int yv = (int)(e.y * 0.05f);             // 24/480
    xv = min(max(xv, 0), SGX - 1);
    yv = min(max(yv, 0), SGY - 1);
    tq = (unsigned int)fmaf(e.z, TQ_SCALE, 0.5f);   // monotone round-to-nearest
    unsigned int pbit = (e.w > 0.0f) ? 0u : 1u;
    unsigned int s = (pbit << 10) | ((unsigned int)yv << 5) | (unsigned int)xv;
    return (s << 21) | tq;
}

// integer-threshold t binning: tv = #{k : tq >= b_k}; pure ALU, no cvt
__device__ __forceinline__ int bin_of_rec(uint32_t r, unsigned int b1, unsigned int b2,
                                          unsigned int b3, unsigned int b4) {
    unsigned int tq = r & 0x1FFFFFu;
    int tv = (int)(tq >= b1) + (int)(tq >= b2) + (int)(tq >= b3) + (int)(tq >= b4);
    unsigned int rest = (r >> 21) & 1023u;   // yv*32 + xv
    unsigned int p    = r >> 31;             // polarity bit
    return tv * 768 + (int)rest + (int)(p * 3840u);
}

__global__ __launch_bounds__(THREADS, 2)
void fused_kernel(const float4* __restrict__ ev, int n,
                  float* __restrict__ out, float inv_s) {
    __shared__ unsigned int sh[NBINS];
    __shared__ unsigned int wmin[32], wmax[32];
    __shared__ unsigned int s_b1, s_b2, s_b3, s_b4;
    __shared__ bool s_last;

    int gtid = blockIdx.x * blockDim.x + threadIdx.x;
    int stride = gridDim.x * blockDim.x;

    // distributed zeroing of the global accumulator (ordered before any flush
    // by the grid-wide sync below)
    for (int b = gtid; b < NBINS; b += stride) g_counts[b] = 0u;

    // ---------------- phase A: stream + pack + minmax ----------------
    unsigned int tqmin = 0xFFFFFFFFu;
    unsigned int tqmax = 0u;
    int i = gtid;

    for (; i + 3 * stride < n; i += 4 * stride) {
        float4 e0 = __ldcs(ev + i);
        float4 e1 = __ldcs(ev + i + stride);
        float4 e2 = __ldcs(ev + i + 2 * stride);
        float4 e3 = __ldcs(ev + i + 3 * stride);
        unsigned int t0, t1, t2, t3;
        uint32_t r0 = pack_event(e0, t0);
        uint32_t r1 = pack_event(e1, t1);
        uint32_t r2 = pack_event(e2, t2);
        uint32_t r3 = pack_event(e3, t3);
        g_rec[i]              = r0;
        g_rec[i + stride]     = r1;
        g_rec[i + 2 * stride] = r2;
        g_rec[i + 3 * stride] = r3;
        tqmin = min(tqmin, min(min(t0, t1), min(t2, t3)));
        tqmax = max(tqmax, max(max(t0, t1), max(t2, t3)));
    }
    #pragma unroll 1
    for (; i < n; i += stride) {
        float4 e = __ldcs(ev + i);
        unsigned int t;
        g_rec[i] = pack_event(e, t);
        tqmin = min(tqmin, t);
        tqmax = max(tqmax, t);
    }

    // block-level minmax reduce
    #pragma unroll
    for (int o = 16; o > 0; o >>= 1) {
        tqmin = min(tqmin, __shfl_xor_sync(0xFFFFFFFFu, tqmin, o));
        tqmax = max(tqmax, __shfl_xor_sync(0xFFFFFFFFu, tqmax, o));
    }
    int wid = threadIdx.x >> 5;
    int lid = threadIdx.x & 31;
    if (lid == 0) { wmin[wid] = tqmin; wmax[wid] = tqmax; }
    __syncthreads();
    if (wid == 0) {
        int nw = blockDim.x >> 5;
        tqmin = (lid < nw) ? wmin[lid] : 0xFFFFFFFFu;
        tqmax = (lid < nw) ? wmax[lid] : 0u;
        #pragma unroll
        for (int o = 16; o > 0; o >>= 1) {
            tqmin = min(tqmin, __shfl_xor_sync(0xFFFFFFFFu, tqmin, o));
            tqmax = max(tqmax, __shfl_xor_sync(0xFFFFFFFFu, tqmax, o));
        }
        if (lid == 0) {
            g_bqmin[blockIdx.x] = tqmin;
            g_bqmax[blockIdx.x] = tqmax;
        }
    }

    // ------------- grid-wide sync (single resident wave) -------------
    // zero smem histogram while other blocks finish streaming
    for (int b = threadIdx.x; b < NBINS; b += blockDim.x) sh[b] = 0u;

    __threadfence();                       // publish rec + partials
    __syncthreads();
    if (threadIdx.x == 0) {
        atomicAdd(&g_arrive, 1u);
        volatile unsigned int* va = &g_arrive;
        while (*va < (unsigned int)gridDim.x) __nanosleep(64);
    }
    __syncthreads();
    __threadfence();                       // acquire: rec + partials visible

    // reduce the 296 partials (every block, redundant but ~300 L2 loads)
    if (threadIdx.x == 0) {
        unsigned int m0 = 0xFFFFFFFFu, m1 = 0u;
        for (int b = 0; b < BLOCKS; b++) {
            m0 = min(m0, g_bqmin[b]);
            m1 = max(m1, g_bqmax[b]);
        }
        if (m1 > m0) {
            unsigned int range = m1 - m0;
            s_b1 = m0 + (1u * range + 4u) / 5u;
            s_b2 = m0 + (2u * range + 4u) / 5u;
            s_b3 = m0 + (3u * range + 4u) / 5u;
            s_b4 = m0 + (4u * range + 4u) / 5u;
        } else {
            // degenerate: raw t binning, tv = int(t*0.1) -> tq >= k*10*TQ_SCALE
            s_b1 = (unsigned int)(10.0 * (double)TQ_SCALE * 1.0 + 0.999999);
            s_b2 = (unsigned int)(10.0 * (double)TQ_SCALE * 2.0 + 0.999999);
            s_b3 = (unsigned int)(10.0 * (double)TQ_SCALE * 3.0 + 0.999999);
            s_b4 = (unsigned int)(10.0 * (double)TQ_SCALE * 4.0 + 0.999999);
        }
    }
    __syncthreads();
    unsigned int b1 = s_b1, b2 = s_b2, b3 = s_b3, b4 = s_b4;

    // ---------------- phase B: histogram (rec L2-hot) ----------------
    const uint4* rec4 = reinterpret_cast<const uint4*>(g_rec);
    int n4 = n >> 2;
    i = blockIdx.x * blockDim.x + threadIdx.x;

    for (; i + stride < n4; i += 2 * stride) {
        uint4 a = rec4[i];
        uint4 b = rec4[i + stride];
        atomicAdd(&sh[bin_of_rec(a.x, b1, b2, b3, b4)], 1u);
        atomicAdd(&sh[bin_of_rec(a.y, b1, b2, b3, b4)], 1u);
        atomicAdd(&sh[bin_of_rec(a.z, b1, b2, b3, b4)], 1u);
        atomicAdd(&sh[bin_of_rec(a.w, b1, b2, b3, b4)], 1u);
        atomicAdd(&sh[bin_of_rec(b.x, b1, b2, b3, b4)], 1u);
        atomicAdd(&sh[bin_of_rec(b.y, b1, b2, b3, b4)], 1u);
        atomicAdd(&sh[bin_of_rec(b.z, b1, b2, b3, b4)], 1u);
        atomicAdd(&sh[bin_of_rec(b.w, b1, b2, b3, b4)], 1u);
    }
    #pragma unroll 1
    for (; i < n4; i += stride) {
        uint4 a = rec4[i];
        atomicAdd(&sh[bin_of_rec(a.x, b1, b2, b3, b4)], 1u);
        atomicAdd(&sh[bin_of_rec(a.y, b1, b2, b3, b4)], 1u);
        atomicAdd(&sh[bin_of_rec(a.z, b1, b2, b3, b4)], 1u);
        atomicAdd(&sh[bin_of_rec(a.w, b1, b2, b3, b4)], 1u);
    }
    #pragma unroll 1
    for (int j = (n4 << 2) + gtid; j < n; j += stride) {
        atomicAdd(&sh[bin_of_rec(g_rec[j], b1, b2, b3, b4)], 1u);
    }

    __syncthreads();
    for (int b = threadIdx.x; b < NBINS; b += blockDim.x) {
        unsigned int v = sh[b];
        if (v) atomicAdd(&g_counts[b], v);
    }

    // ---------------- last-block finalize + counter reset ----------------
    __threadfence();
    __syncthreads();
    if (threadIdx.x == 0) {
        unsigned int t = atomicAdd(&g_done2, 1u);
        s_last = (t == (unsigned int)gridDim.x - 1u);
    }
    __syncthreads();
    if (s_last) {
        __threadfence();
        for (int b = threadIdx.x; b < NBINS; b += blockDim.x)
            out[b] = (float)g_counts[b] * inv_s;
        // all other blocks are past every use of the counters: safe to reset
        // for the next graph replay
        if (threadIdx.x == 0) {
            g_arrive = 0u;
            g_done2  = 0u;
            __threadfence();
        }
    }
}

extern "C" void kernel_launch(void* const* d_in, const int* in_sizes, int n_in,
                              void* d_out, int out_size) {
    const float4* ev = (const float4*)d_in[0];
    int n = in_sizes[0] / 4;              // events: (N, 4) f32, N = 2^24
    float* out = (float*)d_out;

    float inv_s = (n > 0) ? (1.0f / (float)n) : 1.0f;

    fused_kernel<<<BLOCKS, THREADS>>>(ev, n, out, inv_s);
}

// round 7
// speedup vs baseline: 1.0526x; 1.0526x over previous
#include <cuda_runtime.h>
#include <cstdint>

#define SGX 32
#define SGY 24
#define SGT 5
#define NBINS (2 * SGT * SGY * SGX)   // 7680

#define BLOCKS1  592                  // pass1: no smem, high occupancy for MLP
#define THREADS1 256
#define BLOCKS2  296
#define THREADS2 512

#define NPART    (BLOCKS1)

#define N_MAX    16777216
#define TQ_MAX   2097151.0f           // 2^21 - 1
#define TQ_SCALE (TQ_MAX / 50.0f)     // t in [0,50] -> [0, 2^21-1]

__device__ uint32_t g_rec[N_MAX];     // 64 MB packed records
__device__ unsigned int g_counts[NBINS];
__device__ unsigned int g_bqmin[NPART];
__device__ unsigned int g_bqmax[NPART];
__device__ unsigned int g_done;

// rec = (s << 21) | tq, s = p<<10 | yv<<5 | xv
__device__ __forceinline__ uint32_t pack_event(float4 e, unsigned int& tq) {
    int xv = (int)(e.x * 0.05f);             // 32/640
    int yv = (int)(e.y * 0.05f);             // 24/480
    xv = min(max(xv, 0), SGX - 1);
    yv = min(max(yv, 0), SGY - 1);
    tq = (unsigned int)fmaf(e.z, TQ_SCALE, 0.5f);   // monotone round-to-nearest
    unsigned int pbit = (e.w > 0.0f) ? 0u : 1u;
    unsigned int s = (pbit << 10) | ((unsigned int)yv << 5) | (unsigned int)xv;
    return (s << 21) | tq;
}

// ---------------------------------------------------------------------------
// Pass 1: stream events (evict-first), pack records, per-block qmin/qmax,
// zero accumulator + done flag.  No smem -> high occupancy, deep MLP.
// ---------------------------------------------------------------------------
__global__ __launch_bounds__(THREADS1, 8)
void pass1_kernel(const float4* __restrict__ ev, int n) {
    int gtid = blockIdx.x * blockDim.x + threadIdx.x;
    int stride = gridDim.x * blockDim.x;
    for (int b = gtid; b < NBINS; b += stride) g_counts[b] = 0u;
    if (gtid == 0) g_done = 0u;

    unsigned int tqmin = 0xFFFFFFFFu;
    unsigned int tqmax = 0u;
    int i = gtid;

    for (; i + 3 * stride < n; i += 4 * stride) {
        float4 e0 = __ldcs(ev + i);
        float4 e1 = __ldcs(ev + i + stride);
        float4 e2 = __ldcs(ev + i + 2 * stride);
        float4 e3 = __ldcs(ev + i + 3 * stride);
        unsigned int t0, t1, t2, t3;
        uint32_t r0 = pack_event(e0, t0);
        uint32_t r1 = pack_event(e1, t1);
        uint32_t r2 = pack_event(e2, t2);
        uint32_t r3 = pack_event(e3, t3);
        g_rec[i]              = r0;
        g_rec[i + stride]     = r1;
        g_rec[i + 2 * stride] = r2;
        g_rec[i + 3 * stride] = r3;
        tqmin = min(tqmin, min(min(t0, t1), min(t2, t3)));
        tqmax = max(tqmax, max(max(t0, t1), max(t2, t3)));
    }
    #pragma unroll 1
    for (; i < n; i += stride) {
        float4 e = __ldcs(ev + i);
        unsigned int t;
        g_rec[i] = pack_event(e, t);
        tqmin = min(tqmin, t);
        tqmax = max(tqmax, t);
    }

    // warp reduce
    #pragma unroll
    for (int o = 16; o > 0; o >>= 1) {
        tqmin = min(tqmin, __shfl_xor_sync(0xFFFFFFFFu, tqmin, o));
        tqmax = max(tqmax, __shfl_xor_sync(0xFFFFFFFFu, tqmax, o));
    }
    __shared__ unsigned int smin[8], smax[8];
    int wid = threadIdx.x >> 5;
    int lid = threadIdx.x & 31;
    if (lid == 0) { smin[wid] = tqmin; smax[wid] = tqmax; }
    __syncthreads();
    if (wid == 0) {
        int nw = blockDim.x >> 5;
        tqmin = (lid < nw) ? smin[lid] : 0xFFFFFFFFu;
        tqmax = (lid < nw) ? smax[lid] : 0u;
        #pragma unroll
        for (int o = 4; o > 0; o >>= 1) {
            tqmin = min(tqmin, __shfl_xor_sync(0xFFFFFFFFu, tqmin, o));
            tqmax = max(tqmax, __shfl_xor_sync(0xFFFFFFFFu, tqmax, o));
        }
        if (lid == 0) {
            g_bqmin[blockIdx.x] = tqmin;
            g_bqmax[blockIdx.x] = tqmax;
        }
    }
}

// ---------------------------------------------------------------------------
// Pass 2: reduce partials -> 4 integer thresholds, histogram L2-hot records,
// flush, last-block finalize.
// bin = tv*768 + (yv*32+xv) + p*3840, tv = #{k : tq >= b_k}
// ---------------------------------------------------------------------------
__device__ __forceinline__ int bin_of_rec(uint32_t r, unsigned int b1, unsigned int b2,
                                          unsigned int b3, unsigned int b4) {
    unsigned int tq = r & 0x1FFFFFu;
    int tv = (int)(tq >= b1) + (int)(tq >= b2) + (int)(tq >= b3) + (int)(tq >= b4);
    unsigned int rest = (r >> 21) & 1023u;
    unsigned int p    = r >> 31;
    return tv * 768 + (int)rest + (int)(p * 3840u);
}

__global__ __launch_bounds__(THREADS2, 2)
void pass2_kernel(int n, float* __restrict__ out, float inv_s) {
    __shared__ unsigned int sh[NBINS];
    for (int i = threadIdx.x; i < NBINS; i += blockDim.x) sh[i] = 0u;

    // parallel reduce of the per-block partials
    unsigned int tqmin = 0xFFFFFFFFu, tqmax = 0u;
    for (int b = threadIdx.x; b < NPART; b += blockDim.x) {
        tqmin = min(tqmin, g_bqmin[b]);
        tqmax = max(tqmax, g_bqmax[b]);
    }
    #pragma unroll
    for (int o = 16; o > 0; o >>= 1) {
        tqmin = min(tqmin, __shfl_xor_sync(0xFFFFFFFFu, tqmin, o));
        tqmax = max(tqmax, __shfl_xor_sync(0xFFFFFFFFu, tqmax, o));
    }
    __shared__ unsigned int wmin[32], wmax[32];
    __shared__ unsigned int s_b1, s_b2, s_b3, s_b4;
    int wid = threadIdx.x >> 5;
    int lid = threadIdx.x & 31;
    if (lid == 0) { wmin[wid] = tqmin; wmax[wid] = tqmax; }
    __syncthreads();
    if (threadIdx.x == 0) {
        int nw = blockDim.x >> 5;
        unsigned int m0 = wmin[0], m1 = wmax[0];
        for (int w = 1; w < nw; w++) { m0 = min(m0, wmin[w]); m1 = max(m1, wmax[w]); }
        if (m1 > m0) {
            unsigned int range = m1 - m0;
            s_b1 = m0 + (unsigned int)((1ull * range + 4ull) / 5ull);
            s_b2 = m0 + (unsigned int)((2ull * range + 4ull) / 5ull);
            s_b3 = m0 + (unsigned int)((3ull * range + 4ull) / 5ull);
            s_b4 = m0 + (unsigned int)((4ull * range + 4ull) / 5ull);
        } else {
            // degenerate: raw-t binning, tv = int(t*0.1) -> thresholds at k*10
            s_b1 = (unsigned int)(10.0 * (double)TQ_SCALE * 1.0 + 0.999999);
            s_b2 = (unsigned int)(10.0 * (double)TQ_SCALE * 2.0 + 0.999999);
            s_b3 = (unsigned int)(10.0 * (double)TQ_SCALE * 3.0 + 0.999999);
            s_b4 = (unsigned int)(10.0 * (double)TQ_SCALE * 4.0 + 0.999999);
        }
    }
    __syncthreads();
    unsigned int b1 = s_b1, b2 = s_b2, b3 = s_b3, b4 = s_b4;

    const uint4* rec4 = reinterpret_cast<const uint4*>(g_rec);
    int n4 = n >> 2;
    int stride = gridDim.x * blockDim.x;
    int i = blockIdx.x * blockDim.x + threadIdx.x;

    for (; i + stride < n4; i += 2 * stride) {
        uint4 a = rec4[i];
        uint4 b = rec4[i + stride];
        atomicAdd(&sh[bin_of_rec(a.x, b1, b2, b3, b4)], 1u);
        atomicAdd(&sh[bin_of_rec(a.y, b1, b2, b3, b4)], 1u);
        atomicAdd(&sh[bin_of_rec(a.z, b1, b2, b3, b4)], 1u);
        atomicAdd(&sh[bin_of_rec(a.w, b1, b2, b3, b4)], 1u);
        atomicAdd(&sh[bin_of_rec(b.x, b1, b2, b3, b4)], 1u);
        atomicAdd(&sh[bin_of_rec(b.y, b1, b2, b3, b4)], 1u);
        atomicAdd(&sh[bin_of_rec(b.z, b1, b2, b3, b4)], 1u);
        atomicAdd(&sh[bin_of_rec(b.w, b1, b2, b3, b4)], 1u);
    }
    #pragma unroll 1
    for (; i < n4; i += stride) {
        uint4 a = rec4[i];
        atomicAdd(&sh[bin_of_rec(a.x, b1, b2, b3, b4)], 1u);
        atomicAdd(&sh[bin_of_rec(a.y, b1, b2, b3, b4)], 1u);
        atomicAdd(&sh[bin_of_rec(a.z, b1, b2, b3, b4)], 1u);
        atomicAdd(&sh[bin_of_rec(a.w, b1, b2, b3, b4)], 1u);
    }
    #pragma unroll 1
    for (int j = (n4 << 2) + blockIdx.x * blockDim.x + threadIdx.x; j < n; j += stride) {
        atomicAdd(&sh[bin_of_rec(g_rec[j], b1, b2, b3, b4)], 1u);
    }

    __syncthreads();
    for (int b = threadIdx.x; b < NBINS; b += blockDim.x) {
        unsigned int v = sh[b];
        if (v) atomicAdd(&g_counts[b], v);
    }

    // last-block finalize
    __shared__ bool s_last;
    __threadfence();
    __syncthreads();
    if (threadIdx.x == 0) {
        unsigned int t = atomicAdd(&g_done, 1u);
        s_last = (t == gridDim.x - 1);
    }
    __syncthreads();
    if (s_last) {
        __threadfence();
        for (int b = threadIdx.x; b < NBINS; b += blockDim.x)
            out[b] = (float)g_counts[b] * inv_s;
    }
}

extern "C" void kernel_launch(void* const* d_in, const int* in_sizes, int n_in,
                              void* d_out, int out_size) {
    const float4* ev = (const float4*)d_in[0];
    int n = in_sizes[0] / 4;              // events: (N, 4) f32, N = 2^24
    float* out = (float*)d_out;

    float inv_s = (n > 0) ? (1.0f / (float)n) : 1.0f;

    pass1_kernel<<<BLOCKS1, THREADS1>>>(ev, n);
    pass2_kernel<<<BLOCKS2, THREADS2>>>(n, out, inv_s);
}

// round 8
// speedup vs baseline: 1.1373x; 1.0804x over previous
#include <cuda_runtime.h>
#include <cstdint>

#define SGX 32
#define SGY 24
#define SGT 5
#define NBINS (2 * SGT * SGY * SGX)   // 7680

#define BLOCKS   296
#define THREADS1 512
#define THREADS2 1024                 // pass2: 2 CTAs x 1024 = 100% occ/SM

#define N_MAX    16777216
#define TQ_MAX   2097151.0f           // 2^21 - 1
#define TQ_SCALE (TQ_MAX / 50.0f)     // t in [0,50] -> [0, 2^21-1]

__device__ uint32_t g_rec[N_MAX];     // 64 MB packed records
__device__ unsigned int g_counts[NBINS];
__device__ unsigned int g_bqmin[BLOCKS];
__device__ unsigned int g_bqmax[BLOCKS];
__device__ unsigned int g_done;

// rec = (s << 21) | tq, s = p<<10 | yv<<5 | xv
__device__ __forceinline__ uint32_t pack_event(float4 e, unsigned int& tq) {
    int xv = (int)(e.x * 0.05f);             // 32/640
    int yv = (int)(e.y * 0.05f);             // 24/480
    xv = min(max(xv, 0), SGX - 1);
    yv = min(max(yv, 0), SGY - 1);
    tq = (unsigned int)fmaf(e.z, TQ_SCALE, 0.5f);   // monotone round-to-nearest
    unsigned int pbit = (e.w > 0.0f) ? 0u : 1u;
    unsigned int s = (pbit << 10) | ((unsigned int)yv << 5) | (unsigned int)xv;
    return (s << 21) | tq;
}

// ---------------------------------------------------------------------------
// Pass 1: stream events (evict-first), pack records, per-block qmin/qmax,
// zero accumulator + done flag.  (exact R5 configuration)
// ---------------------------------------------------------------------------
__global__ __launch_bounds__(THREADS1, 2)
void pass1_kernel(const float4* __restrict__ ev, int n) {
    int gtid = blockIdx.x * blockDim.x + threadIdx.x;
    int stride = gridDim.x * blockDim.x;
    for (int b = gtid; b < NBINS; b += stride) g_counts[b] = 0u;
    if (gtid == 0) g_done = 0u;

    unsigned int tqmin = 0xFFFFFFFFu;
    unsigned int tqmax = 0u;
    int i = gtid;

    for (; i + 3 * stride < n; i += 4 * stride) {
        float4 e0 = __ldcs(ev + i);
        float4 e1 = __ldcs(ev + i + stride);
        float4 e2 = __ldcs(ev + i + 2 * stride);
        float4 e3 = __ldcs(ev + i + 3 * stride);
        unsigned int t0, t1, t2, t3;
        uint32_t r0 = pack_event(e0, t0);
        uint32_t r1 = pack_event(e1, t1);
        uint32_t r2 = pack_event(e2, t2);
        uint32_t r3 = pack_event(e3, t3);
        g_rec[i]              = r0;
        g_rec[i + stride]     = r1;
        g_rec[i + 2 * stride] = r2;
        g_rec[i + 3 * stride] = r3;
        tqmin = min(tqmin, min(min(t0, t1), min(t2, t3)));
        tqmax = max(tqmax, max(max(t0, t1), max(t2, t3)));
    }
    #pragma unroll 1
    for (; i < n; i += stride) {
        float4 e = __ldcs(ev + i);
        unsigned int t;
        g_rec[i] = pack_event(e, t);
        tqmin = min(tqmin, t);
        tqmax = max(tqmax, t);
    }

    // warp reduce
    #pragma unroll
    for (int o = 16; o > 0; o >>= 1) {
        tqmin = min(tqmin, __shfl_xor_sync(0xFFFFFFFFu, tqmin, o));
        tqmax = max(tqmax, __shfl_xor_sync(0xFFFFFFFFu, tqmax, o));
    }
    __shared__ unsigned int smin[32], smax[32];
    int wid = threadIdx.x >> 5;
    int lid = threadIdx.x & 31;
    if (lid == 0) { smin[wid] = tqmin; smax[wid] = tqmax; }
    __syncthreads();
    if (wid == 0) {
        int nw = blockDim.x >> 5;
        tqmin = (lid < nw) ? smin[lid] : 0xFFFFFFFFu;
        tqmax = (lid < nw) ? smax[lid] : 0u;
        #pragma unroll
        for (int o = 16; o > 0; o >>= 1) {
            tqmin = min(tqmin, __shfl_xor_sync(0xFFFFFFFFu, tqmin, o));
            tqmax = max(tqmax, __shfl_xor_sync(0xFFFFFFFFu, tqmax, o));
        }
        if (lid == 0) {
            g_bqmin[blockIdx.x] = tqmin;
            g_bqmax[blockIdx.x] = tqmax;
        }
    }
}

// ---------------------------------------------------------------------------
// Pass 2: reduce partials, histogram L2-hot records (float decode, R5 form),
// flush, last-block finalize.  1024 threads -> full occupancy.
// ---------------------------------------------------------------------------
__device__ __forceinline__ int bin_of_rec(uint32_t r, unsigned int toff, float sc) {
    unsigned int tq = r & 0x1FFFFFu;
    unsigned int s  = r >> 21;
    int tv = (int)((float)(tq - toff) * sc);     // toff <= tq always (global min)
    tv = min(max(tv, 0), SGT - 1);
    unsigned int rest = s & 1023u;               // yv*32 + xv
    unsigned int p    = s >> 10;
    return tv * 768 + (int)rest + (int)(p * 3840u);
}

__global__ __launch_bounds__(THREADS2, 2)
void pass2_kernel(int n, float* __restrict__ out, float inv_s) {
    __shared__ unsigned int sh[NBINS];
    for (int i = threadIdx.x; i < NBINS; i += blockDim.x) sh[i] = 0u;

    // reduce the per-block partials
    unsigned int tqmin = 0xFFFFFFFFu, tqmax = 0u;
    for (int b = threadIdx.x; b < BLOCKS; b += blockDim.x) {
        tqmin = min(tqmin, g_bqmin[b]);
        tqmax = max(tqmax, g_bqmax[b]);
    }
    #pragma unroll
    for (int o = 16; o > 0; o >>= 1) {
        tqmin = min(tqmin, __shfl_xor_sync(0xFFFFFFFFu, tqmin, o));
        tqmax = max(tqmax, __shfl_xor_sync(0xFFFFFFFFu, tqmax, o));
    }
    __shared__ unsigned int wmin[32], wmax[32];
    __shared__ unsigned int s_toff;
    __shared__ float s_sc;
    int wid = threadIdx.x >> 5;
    int lid = threadIdx.x & 31;
    if (lid == 0) { wmin[wid] = tqmin; wmax[wid] = tqmax; }
    __syncthreads();
    if (threadIdx.x == 0) {
        int nw = blockDim.x >> 5;
        unsigned int m0 = wmin[0], m1 = wmax[0];
        for (int w = 1; w < nw; w++) { m0 = min(m0, wmin[w]); m1 = max(m1, wmax[w]); }
        if (m1 > m0) {
            s_toff = m0;
            s_sc   = 5.0f / (float)(m1 - m0);          // (tq-tqmin)/range * 5
        } else {
            s_toff = 0u;
            s_sc   = 0.1f * (50.0f / TQ_MAX);          // raw t * 0.1 (degenerate)
        }
    }
    __syncthreads();
    unsigned int toff = s_toff;
    float sc = s_sc;

    const uint4* rec4 = reinterpret_cast<const uint4*>(g_rec);
    int n4 = n >> 2;
    int stride = gridDim.x * blockDim.x;
    int i = blockIdx.x * blockDim.x + threadIdx.x;

    // 2 x uint4 (8 events) per iteration for load MLP over L2 hits
    for (; i + stride < n4; i += 2 * stride) {
        uint4 a = rec4[i];
        uint4 b = rec4[i + stride];
        atomicAdd(&sh[bin_of_rec(a.x, toff, sc)], 1u);
        atomicAdd(&sh[bin_of_rec(a.y, toff, sc)], 1u);
        atomicAdd(&sh[bin_of_rec(a.z, toff, sc)], 1u);
        atomicAdd(&sh[bin_of_rec(a.w, toff, sc)], 1u);
        atomicAdd(&sh[bin_of_rec(b.x, toff, sc)], 1u);
        atomicAdd(&sh[bin_of_rec(b.y, toff, sc)], 1u);
        atomicAdd(&sh[bin_of_rec(b.z, toff, sc)], 1u);
        atomicAdd(&sh[bin_of_rec(b.w, toff, sc)], 1u);
    }
    #pragma unroll 1
    for (; i < n4; i += stride) {
        uint4 a = rec4[i];
        atomicAdd(&sh[bin_of_rec(a.x, toff, sc)], 1u);
        atomicAdd(&sh[bin_of_rec(a.y, toff, sc)], 1u);
        atomicAdd(&sh[bin_of_rec(a.z, toff, sc)], 1u);
        atomicAdd(&sh[bin_of_rec(a.w, toff, sc)], 1u);
    }
    // scalar tail (n not multiple of 4)
    #pragma unroll 1
    for (int j = (n4 << 2) + blockIdx.x * blockDim.x + threadIdx.x; j < n; j += stride) {
        atomicAdd(&sh[bin_of_rec(g_rec[j], toff, sc)], 1u);
    }

    __syncthreads();
    for (int b = threadIdx.x; b < NBINS; b += blockDim.x) {
        unsigned int v = sh[b];
        if (v) atomicAdd(&g_counts[b], v);
    }

    // last-block finalize
    __shared__ bool s_last;
    __threadfence();
    __syncthreads();
    if (threadIdx.x == 0) {
        unsigned int t = atomicAdd(&g_done, 1u);
        s_last = (t == gridDim.x - 1);
    }
    __syncthreads();
    if (s_last) {
        __threadfence();
        for (int b = threadIdx.x; b < NBINS; b += blockDim.x)
            out[b] = (float)g_counts[b] * inv_s;
    }
}

extern "C" void kernel_launch(void* const* d_in, const int* in_sizes, int n_in,
                              void* d_out, int out_size) {
    const float4* ev = (const float4*)d_in[0];
    int n = in_sizes[0] / 4;              // events: (N, 4) f32, N = 2^24
    float* out = (float*)d_out;

    float inv_s = (n > 0) ? (1.0f / (float)n) : 1.0f;

    pass1_kernel<<<BLOCKS, THREADS1>>>(ev, n);
    pass2_kernel<<<BLOCKS, THREADS2>>>(n, out, inv_s);
}